// round 11
// baseline (speedup 1.0000x reference)
#include <cuda_runtime.h>
#include <cuda_bf16.h>
#include <cuda_fp16.h>
#include <cstdint>

#define B_SZ   1024
#define K_SZ   512
#define D_SZ   256
#define H_SZ   8
#define HD_SZ  32
#define EPS_LN 1e-5f
#define Q_SCALE 0.17677669529663687f   // 32^-0.5

// ---------------- scratch (device globals; allocation-free) ----------------
__device__ float  g_q[B_SZ * D_SZ];                       // 1 MB
__device__ __half g_kh[(size_t)B_SZ * K_SZ * D_SZ];       // 256 MB (LN'd k, fp16)
__device__ __half g_vh[(size_t)B_SZ * K_SZ * D_SZ];       // 256 MB (v, fp16)
__device__ __half g_wh[2][D_SZ * D_SZ];                   // W fp16 (0=Wk,1=Wv)

// ======================= helpers ==============================
__device__ __forceinline__ uint32_t smem_u32(const void* p) {
    uint32_t a;
    asm("{ .reg .u64 t; cvta.to.shared.u64 t, %1; cvt.u32.u64 %0, t; }"
        : "=r"(a) : "l"(p));
    return a;
}
__device__ __forceinline__ uint32_t pack_h2(float a, float b) {
    __half2 t = __floats2half2_rn(a, b);
    return *reinterpret_cast<uint32_t*>(&t);
}

#define LDSM4(r0, r1, r2, r3, addr) \
    asm volatile("ldmatrix.sync.aligned.m8n8.x4.shared.b16 {%0,%1,%2,%3}, [%4];" \
                 : "=r"(r0), "=r"(r1), "=r"(r2), "=r"(r3) : "r"(addr))

#define MMA16816H(c, a, b) \
    asm volatile("mma.sync.aligned.m16n8k16.row.col.f32.f16.f16.f32 " \
                 "{%0,%1,%2,%3}, {%4,%5,%6,%7}, {%8,%9}, {%0,%1,%2,%3};" \
                 : "+f"((c)[0]), "+f"((c)[1]), "+f"((c)[2]), "+f"((c)[3]) \
                 : "r"((a)[0]), "r"((a)[1]), "r"((a)[2]), "r"((a)[3]), \
                   "r"((b)[0]), "r"((b)[1]))

#define CP16(dst, gsrc) \
    asm volatile("cp.async.ca.shared.global [%0], [%1], 16;" \
                 :: "r"(dst), "l"(gsrc) : "memory")
#define CP_COMMIT() asm volatile("cp.async.commit_group;" ::: "memory")
#define CP_WAIT0()  asm volatile("cp.async.wait_group 0;" ::: "memory")

// ============================================================================
// Kernel 0: convert Wk/Wv to fp16.  grid=512, block=256
// ============================================================================
__global__ void wsplit_kernel(const float* __restrict__ Wk,
                              const float* __restrict__ Wv)
{
    const int sel = blockIdx.x & 1;
    const int i   = (blockIdx.x >> 1) * 256 + threadIdx.x;
    g_wh[sel][i] = __float2half_rn((sel ? Wv : Wk)[i]);
}

// ============================================================================
// Kernel 1: q = LN_perhead(x_q @ Wq^T) * scale          grid=B, block=256
// ============================================================================
__global__ void qproj_kernel(const float* __restrict__ xq,
                             const float* __restrict__ Wq,
                             const float* __restrict__ qn_w,
                             const float* __restrict__ qn_b)
{
    const int b = blockIdx.x;
    const int j = threadIdx.x;
    const int lane = j & 31;

    __shared__ float xrow[D_SZ];
    xrow[j] = xq[b * D_SZ + j];
    __syncthreads();

    const float4* w4 = reinterpret_cast<const float4*>(Wq + (size_t)j * D_SZ);
    const float4* x4 = reinterpret_cast<const float4*>(xrow);
    float acc = 0.f;
#pragma unroll
    for (int d = 0; d < D_SZ / 4; ++d) {
        float4 w = w4[d];
        float4 x = x4[d];
        acc = fmaf(w.x, x.x, acc);
        acc = fmaf(w.y, x.y, acc);
        acc = fmaf(w.z, x.z, acc);
        acc = fmaf(w.w, x.w, acc);
    }
    float s = acc, ss = acc * acc;
#pragma unroll
    for (int o = 16; o > 0; o >>= 1) {
        s  += __shfl_xor_sync(0xffffffffu, s,  o);
        ss += __shfl_xor_sync(0xffffffffu, ss, o);
    }
    const float mu  = s * (1.f / 32.f);
    const float var = ss * (1.f / 32.f) - mu * mu;
    const float r   = rsqrtf(var + EPS_LN);
    float q = (acc - mu) * r * qn_w[lane] + qn_b[lane];
    g_q[b * D_SZ + j] = q * Q_SCALE;
}

// ============================================================================
// Kernel 2 (mma.sync fp16): Out[M,256] = fp16(X) @ fp16(W)^T
//   CTA: 256 thr / 8 warps, M=64, N=256, K chunks 64, double-buffered smem.
//   Warp (mh = wid>>2, hs = wid&3) owns rows [32mh,+32) x cols [64hs,+64)
//   (= heads 2hs, 2hs+1). Target 2 CTAs/SM (83KB smem, <=128 regs).
// ============================================================================
#define CH       64
#define NCH      (D_SZ / CH)      // 4
#define OFF_A    0                 // 64 rows * 128B = 8 KB
#define OFF_W    8192              // 256 rows * 128B = 32 KB
#define STAGE_B  40960             // 40 KB per stage
#define DSM_B    (2 * STAGE_B + 1024)
#define PT       256

template<bool DO_LN>
__global__ void __launch_bounds__(PT, 2)
proj_mma(const float* __restrict__ X, int wsel,
         const float* __restrict__ lnw, const float* __restrict__ lnb)
{
    extern __shared__ char dsm[];
    char* smp = (char*)((((uintptr_t)dsm) + 1023) & ~(uintptr_t)1023);
    const uint32_t base = smem_u32(smp);

    const int tid  = threadIdx.x;
    const int wid  = tid >> 5;
    const int lane = tid & 31;
    const int mh   = wid >> 2;       // 0/1 : 32-row half
    const int hs   = wid & 3;        // 64-col stripe (2 heads)
    const size_t m_base = (size_t)blockIdx.x * 64;

    const __half* __restrict__ Wh = g_wh[wsel];

    float lw[8][2], lb[8][2];
    if (DO_LN) {
#pragma unroll
        for (int j = 0; j < 8; ++j) {
            const int c = (j & 3) * 8 + 2 * (lane & 3);   // channel-in-head
            lw[j][0] = lnw[c];     lw[j][1] = lnw[c + 1];
            lb[j][0] = lnb[c];     lb[j][1] = lnb[c + 1];
        }
    }

    // ---- X load/convert mapping: thread -> row tid>>2, 16 floats ----
    const int xrow = tid >> 2;             // 0..63
    const int fgrp = tid & 3;              // 16-float group in 64-chunk
    const float* xptr = X + (m_base + xrow) * D_SZ + fgrp * 16;
    const uint32_t xb0   = (uint32_t)fgrp * 32u;
    const uint32_t xswz  = (uint32_t)(xrow & 7) * 16u;
    const uint32_t xoff0 = (uint32_t)xrow * 128u + (xb0 ^ xswz);
    const uint32_t xoff1 = (uint32_t)xrow * 128u + ((xb0 + 16u) ^ xswz);

    float acc[2][8][4];
#pragma unroll
    for (int i = 0; i < 2; ++i)
#pragma unroll
        for (int j = 0; j < 8; ++j)
#pragma unroll
            for (int cc = 0; cc < 4; ++cc) acc[i][j][cc] = 0.f;

    float4 xr[4];

    auto stage_x = [&](char* ab) {
        const float* xf = reinterpret_cast<const float*>(xr);
        uint4 h0, h1;
        h0.x = pack_h2(xf[0],  xf[1]);  h0.y = pack_h2(xf[2],  xf[3]);
        h0.z = pack_h2(xf[4],  xf[5]);  h0.w = pack_h2(xf[6],  xf[7]);
        h1.x = pack_h2(xf[8],  xf[9]);  h1.y = pack_h2(xf[10], xf[11]);
        h1.z = pack_h2(xf[12], xf[13]); h1.w = pack_h2(xf[14], xf[15]);
        *reinterpret_cast<uint4*>(ab + OFF_A + xoff0) = h0;
        *reinterpret_cast<uint4*>(ab + OFF_A + xoff1) = h1;
    };

    // ================= prologue: stage 0 = chunk 0 =================
    {
        const uint32_t wb = base;
#pragma unroll
        for (int i = 0; i < 8; ++i) {
            const int idx = tid + i * PT;
            const int row = idx >> 3;
            const int j16 = idx & 7;
            const uint32_t off = (uint32_t)row * 128u +
                                 (((uint32_t)j16 * 16u) ^ ((uint32_t)(row & 7) * 16u));
            CP16(wb + OFF_W + off, (const char*)Wh + (size_t)row * 512 + j16 * 16);
        }
        CP_COMMIT();
#pragma unroll
        for (int u = 0; u < 4; ++u)
            xr[u] = *reinterpret_cast<const float4*>(xptr + u * 4);
        stage_x(smp);
        CP_WAIT0();
        __syncthreads();
    }

    // ================= main loop over K chunks =================
    for (int c = 0; c < NCH; ++c) {
        const int s = c & 1;
        const uint32_t sb = base + s * STAGE_B;

        if (c + 1 < NCH) {
            const int kn = (c + 1) * CH;
            const uint32_t wb = base + (s ^ 1) * STAGE_B;
#pragma unroll
            for (int i = 0; i < 8; ++i) {
                const int idx = tid + i * PT;
                const int row = idx >> 3;
                const int j16 = idx & 7;
                const uint32_t off = (uint32_t)row * 128u +
                                     (((uint32_t)j16 * 16u) ^ ((uint32_t)(row & 7) * 16u));
                CP16(wb + OFF_W + off,
                     (const char*)Wh + (size_t)row * 512 + kn * 2 + j16 * 16);
            }
            CP_COMMIT();
#pragma unroll
            for (int u = 0; u < 4; ++u)
                xr[u] = *reinterpret_cast<const float4*>(xptr + kn + u * 4);
        }

        // ---------------- compute chunk c ----------------
#pragma unroll
        for (int ks = 0; ks < 4; ++ks) {
            uint32_t Ah4[2][4], Bh4[8][2];
            {
                const int ar = lane & 15;
                const uint32_t akhb = (uint32_t)(lane >> 4) * 16u;
#pragma unroll
                for (int i = 0; i < 2; ++i) {
                    const int row = 32 * mh + 16 * i + ar;
                    const uint32_t off = (uint32_t)row * 128u +
                        (((uint32_t)ks * 32u + akhb) ^ ((uint32_t)(row & 7) * 16u));
                    LDSM4(Ah4[i][0], Ah4[i][1], Ah4[i][2], Ah4[i][3], sb + OFF_A + off);
                }
            }
            {
                const int g2  = lane >> 3;
                const uint32_t khb = (uint32_t)(g2 & 1) * 16u;
                const int rsub = ((g2 >> 1) * 8) + (lane & 7);
#pragma unroll
                for (int p = 0; p < 4; ++p) {
                    const int row = hs * 64 + p * 16 + rsub;
                    const uint32_t off = (uint32_t)row * 128u +
                        (((uint32_t)ks * 32u + khb) ^ ((uint32_t)(row & 7) * 16u));
                    LDSM4(Bh4[2 * p][0], Bh4[2 * p][1], Bh4[2 * p + 1][0], Bh4[2 * p + 1][1],
                          sb + OFF_W + off);
                }
            }
#pragma unroll
            for (int i = 0; i < 2; ++i)
#pragma unroll
                for (int j = 0; j < 8; ++j)
                    MMA16816H(acc[i][j], Ah4[i], Bh4[j]);
        }

        // ---------------- stage X for chunk c+1 ----------------
        if (c + 1 < NCH) {
            stage_x(smp + (s ^ 1) * STAGE_B);
            CP_WAIT0();
        }
        __syncthreads();
    }

    // ================= epilogue: per-head LN + fp16 store =================
    __half* __restrict__ Out = DO_LN ? g_kh : g_vh;
    const int g  = lane >> 2;
    const int tg = lane & 3;

#pragma unroll
    for (int i = 0; i < 2; ++i) {
#pragma unroll
        for (int half = 0; half < 2; ++half) {
            const int r = 32 * mh + 16 * i + 8 * half + g;
            float v0[8], v1[8];
#pragma unroll
            for (int j = 0; j < 8; ++j) {
                v0[j] = acc[i][j][2 * half];
                v1[j] = acc[i][j][2 * half + 1];
            }
            if (DO_LN) {
#pragma unroll
                for (int hd = 0; hd < 2; ++hd) {
                    float s = 0.f, ss = 0.f;
#pragma unroll
                    for (int jj = 0; jj < 4; ++jj) {
                        const int j = hd * 4 + jj;
                        s  += v0[j] + v1[j];
                        ss += v0[j] * v0[j] + v1[j] * v1[j];
                    }
                    s  += __shfl_xor_sync(0xffffffffu, s,  1);
                    ss += __shfl_xor_sync(0xffffffffu, ss, 1);
                    s  += __shfl_xor_sync(0xffffffffu, s,  2);
                    ss += __shfl_xor_sync(0xffffffffu, ss, 2);
                    const float mu  = s * (1.f / 32.f);
                    const float var = ss * (1.f / 32.f) - mu * mu;
                    const float rr  = rsqrtf(var + EPS_LN);
#pragma unroll
                    for (int jj = 0; jj < 4; ++jj) {
                        const int j = hd * 4 + jj;
                        v0[j] = (v0[j] - mu) * rr * lw[j][0] + lb[j][0];
                        v1[j] = (v1[j] - mu) * rr * lw[j][1] + lb[j][1];
                    }
                }
            }
            __half* orow = Out + (m_base + r) * D_SZ + hs * 64 + 2 * tg;
#pragma unroll
            for (int j = 0; j < 8; ++j)
                *reinterpret_cast<__half2*>(orow + 8 * j) = __floats2half2_rn(v0[j], v1[j]);
        }
    }
}

// ============================================================================
// Kernel 3: attention over fp16 k/v. grid=B, block=512.
//   2 warps per head (K split); within a warp, lane halves (rh) take
//   alternate rows, each lane owns 2 channels via __half2 -> 16 rows/set.
//   4-way flash-state merge in smem, block LN, Wp GEMV.
// ============================================================================
#define ATTN_SETS 16   // per warp: 256 rows / 16

__global__ void __launch_bounds__(512, 2)
attn_kernel(const float* __restrict__ Wp,
            const float* __restrict__ n_w,
            const float* __restrict__ n_b,
            float* __restrict__ out)
{
    const int b    = blockIdx.x;
    const int tid  = threadIdx.x;
    const int w    = tid >> 5;
    const int lane = tid & 31;
    const int h    = w & 7;
    const int khalf = w >> 3;      // 0/1 : K rows [0,256) or [256,512)
    const int rh   = lane >> 4;    // row parity within pair
    const int cl   = lane & 15;    // channel-pair index

    float2 q2;
    {
        const float* qp = g_q + b * D_SZ + h * HD_SZ + 2 * cl;
        q2.x = qp[0]; q2.y = qp[1];
    }

    const __half* kp = g_kh + (size_t)b * K_SZ * D_SZ + (size_t)khalf * 256 * D_SZ
                            + h * HD_SZ + 2 * cl;
    const __half* vp = g_vh + (size_t)b * K_SZ * D_SZ + (size_t)khalf * 256 * D_SZ
                            + h * HD_SZ + 2 * cl;

    float m = -1e30f, l = 0.f;
    float2 o = make_float2(0.f, 0.f);

    __half2 ka[8], va[8], kb[8], vb[8];

#define LOADSET(s, K, V) do {                                             \
    _Pragma("unroll")                                                     \
    for (int u = 0; u < 8; ++u) {                                         \
        const int row = (s) * 16 + 2 * u + rh;                            \
        K[u] = *reinterpret_cast<const __half2*>(kp + (size_t)row * D_SZ);\
        V[u] = *reinterpret_cast<const __half2*>(vp + (size_t)row * D_SZ);\
    } } while (0)

#define PROCESS(K, V) do {                                                \
    float s8[8];                                                          \
    _Pragma("unroll")                                                     \
    for (int u = 0; u < 8; ++u) {                                         \
        const float2 kf = __half22float2(K[u]);                           \
        s8[u] = fmaf(q2.x, kf.x, q2.y * kf.y);                            \
    }                                                                     \
    _Pragma("unroll")                                                     \
    for (int off = 8; off > 0; off >>= 1) {                               \
        _Pragma("unroll")                                                 \
        for (int u = 0; u < 8; ++u)                                       \
            s8[u] += __shfl_xor_sync(0xffffffffu, s8[u], off);            \
    }                                                                     \
    float mb = s8[0];                                                     \
    _Pragma("unroll")                                                     \
    for (int u = 1; u < 8; ++u) mb = fmaxf(mb, s8[u]);                    \
    const float mn   = fmaxf(m, mb);                                      \
    const float corr = __expf(m - mn);                                    \
    l *= corr;  o.x *= corr;  o.y *= corr;                                \
    _Pragma("unroll")                                                     \
    for (int u = 0; u < 8; ++u) {                                         \
        const float p = __expf(s8[u] - mn);                               \
        const float2 vf = __half22float2(V[u]);                           \
        l += p;                                                           \
        o.x = fmaf(p, vf.x, o.x);                                         \
        o.y = fmaf(p, vf.y, o.y);                                         \
    }                                                                     \
    m = mn; } while (0)

    LOADSET(0, ka, va);
#pragma unroll 1
    for (int it = 0; it < ATTN_SETS; it += 2) {
        LOADSET(it + 1, kb, vb);
        PROCESS(ka, va);
        if (it + 2 < ATTN_SETS) LOADSET(it + 2, ka, va);
        PROCESS(kb, vb);
    }
#undef LOADSET
#undef PROCESS

    // ---- merge 4 states per head (2 warps x 2 lane-halves) ----
    __shared__ float  sm32[32], sl32[32];
    __shared__ float2 so32[32][17];
    const int sidx = w * 2 + rh;
    if (cl == 0) { sm32[sidx] = m; sl32[sidx] = l; }
    so32[sidx][cl] = o;
    __syncthreads();

    float o_val = 0.f;
    if (tid < 256) {
        const int hh  = tid >> 5;      // head
        const int ch  = tid & 31;      // channel in head
        const int cl2 = ch >> 1;
        const int comp = ch & 1;
        const int i0 = hh * 2, i1 = hh * 2 + 1;
        const int i2 = (hh + 8) * 2, i3 = (hh + 8) * 2 + 1;
        const float m0 = sm32[i0], m1 = sm32[i1], m2 = sm32[i2], m3 = sm32[i3];
        const float M = fmaxf(fmaxf(m0, m1), fmaxf(m2, m3));
        const float c0 = __expf(m0 - M), c1 = __expf(m1 - M);
        const float c2 = __expf(m2 - M), c3 = __expf(m3 - M);
        const float L = sl32[i0] * c0 + sl32[i1] * c1 + sl32[i2] * c2 + sl32[i3] * c3;
        const float2 ov0 = so32[i0][cl2], ov1 = so32[i1][cl2];
        const float2 ov2 = so32[i2][cl2], ov3 = so32[i3][cl2];
        const float num = comp
            ? (ov0.y * c0 + ov1.y * c1 + ov2.y * c2 + ov3.y * c3)
            : (ov0.x * c0 + ov1.x * c1 + ov2.x * c2 + ov3.x * c3);
        o_val = num / L;
    }

    // ---- block LN over 256 channels (threads 0..255 hold o_val) ----
    __shared__ float sred[2][8];
    if (tid < 256) {
        float s = o_val, ss = o_val * o_val;
#pragma unroll
        for (int off = 16; off > 0; off >>= 1) {
            s  += __shfl_xor_sync(0xffffffffu, s,  off);
            ss += __shfl_xor_sync(0xffffffffu, ss, off);
        }
        if (lane == 0) { sred[0][w] = s; sred[1][w] = ss; }
    }
    __syncthreads();
    float ts = 0.f, tss = 0.f;
#pragma unroll
    for (int i = 0; i < 8; ++i) { ts += sred[0][i]; tss += sred[1][i]; }
    const float mu  = ts * (1.f / 256.f);
    const float var = tss * (1.f / 256.f) - mu * mu;
    const float rln = rsqrtf(var + EPS_LN);

    __shared__ float sn[D_SZ];
    if (tid < 256)
        sn[tid] = (o_val - mu) * rln * n_w[tid] + n_b[tid];
    __syncthreads();

    // ---- out @ Wp^T : 2 threads per output column (split K 128+128) ----
    const int c   = tid & 255;
    const int seg = tid >> 8;
    const float4* w4 = reinterpret_cast<const float4*>(Wp + (size_t)c * D_SZ + seg * 128);
    const float4* x4 = reinterpret_cast<const float4*>(sn + seg * 128);
    float a = 0.f;
#pragma unroll
    for (int d = 0; d < 32; ++d) {
        float4 wv = w4[d];
        float4 xv = x4[d];
        a = fmaf(wv.x, xv.x, a);
        a = fmaf(wv.y, xv.y, a);
        a = fmaf(wv.z, xv.z, a);
        a = fmaf(wv.w, xv.w, a);
    }
    __shared__ float part[256];
    if (seg == 1) part[c] = a;
    __syncthreads();
    if (seg == 0) out[b * D_SZ + c] = a + part[c];
}

// ============================================================================
extern "C" void kernel_launch(void* const* d_in, const int* in_sizes, int n_in,
                              void* d_out, int out_size)
{
    const float* x_q  = (const float*)d_in[0];
    const float* x_k  = (const float*)d_in[1];
    const float* x_v  = (const float*)d_in[2];
    const float* Wq   = (const float*)d_in[3];
    const float* Wk   = (const float*)d_in[4];
    const float* Wv   = (const float*)d_in[5];
    const float* Wp   = (const float*)d_in[6];
    const float* qn_w = (const float*)d_in[7];
    const float* qn_b = (const float*)d_in[8];
    const float* kn_w = (const float*)d_in[9];
    const float* kn_b = (const float*)d_in[10];
    const float* n_w  = (const float*)d_in[11];
    const float* n_b  = (const float*)d_in[12];
    float* out = (float*)d_out;

    cudaFuncSetAttribute(proj_mma<true>,
                         cudaFuncAttributeMaxDynamicSharedMemorySize, DSM_B);
    cudaFuncSetAttribute(proj_mma<false>,
                         cudaFuncAttributeMaxDynamicSharedMemorySize, DSM_B);
    cudaFuncSetAttribute(proj_mma<true>,
                         cudaFuncAttributePreferredSharedMemoryCarveout, 100);
    cudaFuncSetAttribute(proj_mma<false>,
                         cudaFuncAttributePreferredSharedMemoryCarveout, 100);

    const int M_TILES = (B_SZ * K_SZ) / 64;   // 8192

    wsplit_kernel<<<512, 256>>>(Wk, Wv);
    qproj_kernel<<<B_SZ, 256>>>(x_q, Wq, qn_w, qn_b);
    proj_mma<true ><<<M_TILES, PT, DSM_B>>>(x_k, 0, kn_w, kn_b);
    proj_mma<false><<<M_TILES, PT, DSM_B>>>(x_v, 1, nullptr, nullptr);
    attn_kernel<<<B_SZ, 512>>>(Wp, n_w, n_b, out);
}

// round 12
// speedup vs baseline: 1.6002x; 1.6002x over previous
#include <cuda_runtime.h>
#include <cuda_bf16.h>
#include <cuda_fp16.h>
#include <cstdint>

#define B_SZ   1024
#define K_SZ   512
#define D_SZ   256
#define H_SZ   8
#define HD_SZ  32
#define EPS_LN 1e-5f
#define Q_SCALE 0.17677669529663687f   // 32^-0.5

// ---------------- scratch (device globals; allocation-free) ----------------
__device__ float  g_q[B_SZ * D_SZ];                       // 1 MB
__device__ __half g_kh[(size_t)B_SZ * K_SZ * D_SZ];       // 256 MB (LN'd k, fp16)
__device__ __half g_vh[(size_t)B_SZ * K_SZ * D_SZ];       // 256 MB (v, fp16)
__device__ __half g_wh[2][D_SZ * D_SZ];                   // W fp16 (0=Wk,1=Wv)

// ======================= helpers ==============================
__device__ __forceinline__ uint32_t smem_u32(const void* p) {
    uint32_t a;
    asm("{ .reg .u64 t; cvta.to.shared.u64 t, %1; cvt.u32.u64 %0, t; }"
        : "=r"(a) : "l"(p));
    return a;
}
__device__ __forceinline__ uint32_t pack_h2(float a, float b) {
    __half2 t = __floats2half2_rn(a, b);
    return *reinterpret_cast<uint32_t*>(&t);
}

#define LDSM4(r0, r1, r2, r3, addr) \
    asm volatile("ldmatrix.sync.aligned.m8n8.x4.shared.b16 {%0,%1,%2,%3}, [%4];" \
                 : "=r"(r0), "=r"(r1), "=r"(r2), "=r"(r3) : "r"(addr))

#define MMA16816H(c, a, b) \
    asm volatile("mma.sync.aligned.m16n8k16.row.col.f32.f16.f16.f32 " \
                 "{%0,%1,%2,%3}, {%4,%5,%6,%7}, {%8,%9}, {%0,%1,%2,%3};" \
                 : "+f"((c)[0]), "+f"((c)[1]), "+f"((c)[2]), "+f"((c)[3]) \
                 : "r"((a)[0]), "r"((a)[1]), "r"((a)[2]), "r"((a)[3]), \
                   "r"((b)[0]), "r"((b)[1]))

#define CP16(dst, gsrc) \
    asm volatile("cp.async.ca.shared.global [%0], [%1], 16;" \
                 :: "r"(dst), "l"(gsrc) : "memory")
#define CP_COMMIT() asm volatile("cp.async.commit_group;" ::: "memory")
#define CP_WAIT0()  asm volatile("cp.async.wait_group 0;" ::: "memory")

// ============================================================================
// Kernel 0: convert Wk/Wv to fp16.  grid=512, block=256
// ============================================================================
__global__ void wsplit_kernel(const float* __restrict__ Wk,
                              const float* __restrict__ Wv)
{
    const int sel = blockIdx.x & 1;
    const int i   = (blockIdx.x >> 1) * 256 + threadIdx.x;
    g_wh[sel][i] = __float2half_rn((sel ? Wv : Wk)[i]);
}

// ============================================================================
// Kernel 1: q = LN_perhead(x_q @ Wq^T) * scale          grid=B, block=256
// ============================================================================
__global__ void qproj_kernel(const float* __restrict__ xq,
                             const float* __restrict__ Wq,
                             const float* __restrict__ qn_w,
                             const float* __restrict__ qn_b)
{
    const int b = blockIdx.x;
    const int j = threadIdx.x;
    const int lane = j & 31;

    __shared__ float xrow[D_SZ];
    xrow[j] = xq[b * D_SZ + j];
    __syncthreads();

    const float4* w4 = reinterpret_cast<const float4*>(Wq + (size_t)j * D_SZ);
    const float4* x4 = reinterpret_cast<const float4*>(xrow);
    float acc = 0.f;
#pragma unroll
    for (int d = 0; d < D_SZ / 4; ++d) {
        float4 w = w4[d];
        float4 x = x4[d];
        acc = fmaf(w.x, x.x, acc);
        acc = fmaf(w.y, x.y, acc);
        acc = fmaf(w.z, x.z, acc);
        acc = fmaf(w.w, x.w, acc);
    }
    float s = acc, ss = acc * acc;
#pragma unroll
    for (int o = 16; o > 0; o >>= 1) {
        s  += __shfl_xor_sync(0xffffffffu, s,  o);
        ss += __shfl_xor_sync(0xffffffffu, ss, o);
    }
    const float mu  = s * (1.f / 32.f);
    const float var = ss * (1.f / 32.f) - mu * mu;
    const float r   = rsqrtf(var + EPS_LN);
    float q = (acc - mu) * r * qn_w[lane] + qn_b[lane];
    g_q[b * D_SZ + j] = q * Q_SCALE;
}

// ============================================================================
// Kernel 2 (mma.sync fp16, 1-pass): both K and V projections in one launch.
//   grid=(8192, 2): blockIdx.y selects (X, W, LN?, Out).
//   CTA: 512 thr / 16 warps, M=64, N=256, K chunks 64, double-buffered smem.
//   Warp (mh = wid>>3, h = wid&7) owns rows [32mh,+32) x cols [32h,+32).
//   (Exact R9 mainloop — known 341us/GEMM config.)
// ============================================================================
#define CH       64
#define NCH      (D_SZ / CH)      // 4
#define OFF_A    0                 // 64 rows * 128B = 8 KB
#define OFF_W    8192              // 256 rows * 128B = 32 KB
#define STAGE_B  40960             // 40 KB per stage
#define DSM_B    (2 * STAGE_B + 1024)
#define PT       512

__global__ void __launch_bounds__(PT, 1)
proj_mma(const float* __restrict__ x_k, const float* __restrict__ x_v,
         const float* __restrict__ lnw, const float* __restrict__ lnb)
{
    extern __shared__ char dsm[];
    char* smp = (char*)((((uintptr_t)dsm) + 1023) & ~(uintptr_t)1023);
    const uint32_t base = smem_u32(smp);

    const int wsel = blockIdx.y;           // 0 = K (with LN), 1 = V
    const bool do_ln = (wsel == 0);
    const float* __restrict__ X = do_ln ? x_k : x_v;

    const int tid  = threadIdx.x;
    const int wid  = tid >> 5;
    const int lane = tid & 31;
    const int mh   = wid >> 3;       // 0/1 : 32-row half
    const int h    = wid & 7;        // head / 32-col stripe
    const size_t m_base = (size_t)blockIdx.x * 64;

    const __half* __restrict__ Wh = g_wh[wsel];

    float lw[4][2], lb[4][2];
    if (do_ln) {
#pragma unroll
        for (int j = 0; j < 4; ++j) {
            const int c = 8 * j + 2 * (lane & 3);
            lw[j][0] = lnw[c];     lw[j][1] = lnw[c + 1];
            lb[j][0] = lnb[c];     lb[j][1] = lnb[c + 1];
        }
    }

    // ---- X load/convert mapping: thread -> row tid>>3, 8 floats ----
    const int xrow = tid >> 3;             // 0..63
    const int xc8  = tid & 7;              // 8-float group in 64-chunk
    const float* xptr = X + (m_base + xrow) * D_SZ + xc8 * 8;
    const uint32_t xoff = (uint32_t)xrow * 128u +
                          (((uint32_t)xc8 * 16u) ^ ((uint32_t)(xrow & 7) * 16u));

    float acc[2][4][4];
#pragma unroll
    for (int i = 0; i < 2; ++i)
#pragma unroll
        for (int j = 0; j < 4; ++j)
#pragma unroll
            for (int cc = 0; cc < 4; ++cc) acc[i][j][cc] = 0.f;

    float4 xr[2];

    auto stage_x = [&](char* ab) {
        const float* xf = reinterpret_cast<const float*>(xr);
        uint4 hv;
        hv.x = pack_h2(xf[0], xf[1]); hv.y = pack_h2(xf[2], xf[3]);
        hv.z = pack_h2(xf[4], xf[5]); hv.w = pack_h2(xf[6], xf[7]);
        *reinterpret_cast<uint4*>(ab + OFF_A + xoff) = hv;
    };

    // ================= prologue: stage 0 = chunk 0 =================
    {
        const uint32_t wb = base;
#pragma unroll
        for (int i = 0; i < 4; ++i) {
            const int idx = tid + i * PT;
            const int row = idx >> 3;
            const int j16 = idx & 7;
            const uint32_t off = (uint32_t)row * 128u +
                                 (((uint32_t)j16 * 16u) ^ ((uint32_t)(row & 7) * 16u));
            CP16(wb + OFF_W + off, (const char*)Wh + (size_t)row * 512 + j16 * 16);
        }
        CP_COMMIT();
        xr[0] = *reinterpret_cast<const float4*>(xptr);
        xr[1] = *reinterpret_cast<const float4*>(xptr + 4);
        stage_x(smp);
        CP_WAIT0();
        __syncthreads();
    }

    // ================= main loop over K chunks =================
    for (int c = 0; c < NCH; ++c) {
        const int s = c & 1;
        const uint32_t sb = base + s * STAGE_B;

        if (c + 1 < NCH) {
            const int kn = (c + 1) * CH;
            const uint32_t wb = base + (s ^ 1) * STAGE_B;
#pragma unroll
            for (int i = 0; i < 4; ++i) {
                const int idx = tid + i * PT;
                const int row = idx >> 3;
                const int j16 = idx & 7;
                const uint32_t off = (uint32_t)row * 128u +
                                     (((uint32_t)j16 * 16u) ^ ((uint32_t)(row & 7) * 16u));
                CP16(wb + OFF_W + off,
                     (const char*)Wh + (size_t)row * 512 + kn * 2 + j16 * 16);
            }
            CP_COMMIT();
            xr[0] = *reinterpret_cast<const float4*>(xptr + kn);
            xr[1] = *reinterpret_cast<const float4*>(xptr + kn + 4);
        }

        // ---------------- compute chunk c ----------------
#pragma unroll
        for (int ks = 0; ks < 4; ++ks) {
            uint32_t Ah4[2][4], Bh4[4][2];
            {
                const int ar = lane & 15;
                const uint32_t akhb = (uint32_t)(lane >> 4) * 16u;
#pragma unroll
                for (int i = 0; i < 2; ++i) {
                    const int row = 32 * mh + 16 * i + ar;
                    const uint32_t off = (uint32_t)row * 128u +
                        (((uint32_t)ks * 32u + akhb) ^ ((uint32_t)(row & 7) * 16u));
                    LDSM4(Ah4[i][0], Ah4[i][1], Ah4[i][2], Ah4[i][3], sb + OFF_A + off);
                }
            }
            {
                const int g2  = lane >> 3;
                const uint32_t khb = (uint32_t)(g2 & 1) * 16u;
                const int rsub = ((g2 >> 1) * 8) + (lane & 7);
#pragma unroll
                for (int p = 0; p < 2; ++p) {
                    const int row = h * 32 + p * 16 + rsub;
                    const uint32_t off = (uint32_t)row * 128u +
                        (((uint32_t)ks * 32u + khb) ^ ((uint32_t)(row & 7) * 16u));
                    LDSM4(Bh4[2 * p][0], Bh4[2 * p][1], Bh4[2 * p + 1][0], Bh4[2 * p + 1][1],
                          sb + OFF_W + off);
                }
            }
#pragma unroll
            for (int i = 0; i < 2; ++i)
#pragma unroll
                for (int j = 0; j < 4; ++j)
                    MMA16816H(acc[i][j], Ah4[i], Bh4[j]);
        }

        // ---------------- stage X for chunk c+1 ----------------
        if (c + 1 < NCH) {
            stage_x(smp + (s ^ 1) * STAGE_B);
            CP_WAIT0();
        }
        __syncthreads();
    }

    // ================= epilogue: per-head LN + fp16 store =================
    __half* __restrict__ Out = do_ln ? g_kh : g_vh;
    const int g  = lane >> 2;
    const int tg = lane & 3;
    const int ncol = h * 32 + 2 * tg;

#pragma unroll
    for (int i = 0; i < 2; ++i) {
#pragma unroll
        for (int half = 0; half < 2; ++half) {
            const int r = 32 * mh + 16 * i + 8 * half + g;
            float v0[4], v1[4];
#pragma unroll
            for (int j = 0; j < 4; ++j) {
                v0[j] = acc[i][j][2 * half];
                v1[j] = acc[i][j][2 * half + 1];
            }
            if (do_ln) {
                float s = 0.f, ss = 0.f;
#pragma unroll
                for (int j = 0; j < 4; ++j) {
                    s  += v0[j] + v1[j];
                    ss += v0[j] * v0[j] + v1[j] * v1[j];
                }
                s  += __shfl_xor_sync(0xffffffffu, s,  1);
                ss += __shfl_xor_sync(0xffffffffu, ss, 1);
                s  += __shfl_xor_sync(0xffffffffu, s,  2);
                ss += __shfl_xor_sync(0xffffffffu, ss, 2);
                const float mu  = s * (1.f / 32.f);
                const float var = ss * (1.f / 32.f) - mu * mu;
                const float rr  = rsqrtf(var + EPS_LN);
#pragma unroll
                for (int j = 0; j < 4; ++j) {
                    v0[j] = (v0[j] - mu) * rr * lw[j][0] + lb[j][0];
                    v1[j] = (v1[j] - mu) * rr * lw[j][1] + lb[j][1];
                }
            }
            __half* orow = Out + (m_base + r) * D_SZ + ncol;
#pragma unroll
            for (int j = 0; j < 4; ++j)
                *reinterpret_cast<__half2*>(orow + 8 * j) = __floats2half2_rn(v0[j], v1[j]);
        }
    }
}

// ============================================================================
// Kernel 3: attention over fp16 k/v. grid=B, block=512, 2 CTAs/SM.
//   2 warps per head (K split). Lane = (row-group rg=lane>>2, slice cs=lane&3):
//   one uint4 load = full 64B head-row slice -> warp covers 8 rows per LDG.128.
//   2-row-batched flash updates; 3-round shuffle merge; cross-warp via smem.
// ============================================================================
__global__ void __launch_bounds__(512, 2)
attn_kernel(const float* __restrict__ Wp,
            const float* __restrict__ n_w,
            const float* __restrict__ n_b,
            float* __restrict__ out)
{
    const int b    = blockIdx.x;
    const int tid  = threadIdx.x;
    const int w    = tid >> 5;
    const int lane = tid & 31;
    const int h    = w & 7;
    const int khalf = w >> 3;      // 0/1 : K rows [0,256) or [256,512)
    const int rg   = lane >> 2;    // row within 8-row group
    const int cs   = lane & 3;     // 8-channel slice

    // q slice: channels h*32 + cs*8 .. +8
    float qv[8];
    {
        const float4* qp = reinterpret_cast<const float4*>(
            g_q + b * D_SZ + h * HD_SZ + cs * 8);
        float4 a = qp[0], c = qp[1];
        qv[0] = a.x; qv[1] = a.y; qv[2] = a.z; qv[3] = a.w;
        qv[4] = c.x; qv[5] = c.y; qv[6] = c.z; qv[7] = c.w;
    }

    const __half* kbase = g_kh + (size_t)b * K_SZ * D_SZ + (size_t)khalf * 256 * D_SZ
                               + h * HD_SZ + cs * 8;
    const __half* vbase = g_vh + (size_t)b * K_SZ * D_SZ + (size_t)khalf * 256 * D_SZ
                               + h * HD_SZ + cs * 8;

    float m = -1e30f, l = 0.f;
    float acc[8];
#pragma unroll
    for (int e = 0; e < 8; ++e) acc[e] = 0.f;

    // 32 row-groups of 8 rows per warp; pipeline 2 (k,v) uint4 loads ahead.
    uint4 ka, va, kb, vb;

#define ALOAD(i, K, V) do {                                                    \
    const size_t roff = (size_t)((i) * 8 + rg) * D_SZ;                         \
    K = *reinterpret_cast<const uint4*>(kbase + roff);                         \
    V = *reinterpret_cast<const uint4*>(vbase + roff);                         \
} while (0)

#define ADOT(K, sres) do {                                                     \
    const __half2* kh = reinterpret_cast<const __half2*>(&K);                  \
    float s = 0.f;                                                             \
    _Pragma("unroll")                                                          \
    for (int e = 0; e < 4; ++e) {                                              \
        const float2 kf = __half22float2(kh[e]);                               \
        s = fmaf(qv[2 * e], kf.x, s);                                          \
        s = fmaf(qv[2 * e + 1], kf.y, s);                                      \
    }                                                                          \
    s += __shfl_xor_sync(0xffffffffu, s, 1);                                   \
    s += __shfl_xor_sync(0xffffffffu, s, 2);                                   \
    sres = s;                                                                  \
} while (0)

    ALOAD(0, ka, va);
#pragma unroll 1
    for (int it = 0; it < 32; it += 2) {
        ALOAD(it + 1, kb, vb);
        float s0, s1;
        ADOT(ka, s0);
        if (it + 2 < 32) { /* prefetch next pair's first set after using ka */ }
        ADOT(kb, s1);

        const float mn   = fmaxf(m, fmaxf(s0, s1));
        const float corr = __expf(m - mn);
        const float p0   = __expf(s0 - mn);
        const float p1   = __expf(s1 - mn);
        l = l * corr + p0 + p1;
        const __half2* v0h = reinterpret_cast<const __half2*>(&va);
        const __half2* v1h = reinterpret_cast<const __half2*>(&vb);
#pragma unroll
        for (int e = 0; e < 4; ++e) {
            const float2 vf0 = __half22float2(v0h[e]);
            const float2 vf1 = __half22float2(v1h[e]);
            acc[2 * e]     = fmaf(acc[2 * e],     corr, p0 * vf0.x + p1 * vf1.x);
            acc[2 * e + 1] = fmaf(acc[2 * e + 1], corr, p0 * vf0.y + p1 * vf1.y);
        }
        m = mn;
        if (it + 2 < 32) ALOAD(it + 2, ka, va);
    }
#undef ALOAD
#undef ADOT

    // ---- intra-warp merge over 8 row-groups (lanes xor 4,8,16) ----
#pragma unroll
    for (int off = 4; off <= 16; off <<= 1) {
        const float pm = __shfl_xor_sync(0xffffffffu, m, off);
        const float pl = __shfl_xor_sync(0xffffffffu, l, off);
        const float MM = fmaxf(m, pm);
        const float ca = __expf(m - MM);
        const float cb = __expf(pm - MM);
        l = l * ca + pl * cb;
#pragma unroll
        for (int e = 0; e < 8; ++e) {
            const float pa = __shfl_xor_sync(0xffffffffu, acc[e], off);
            acc[e] = acc[e] * ca + pa * cb;
        }
        m = MM;
    }

    // ---- cross-warp merge (w and w+8 share a head) ----
    __shared__ float sm[16], sl[16];
    __shared__ float sacc[16][33];
    if (lane == 0) { sm[w] = m; sl[w] = l; }
    if (rg == 0) {
#pragma unroll
        for (int e = 0; e < 8; ++e) sacc[w][cs * 8 + e] = acc[e];
    }
    __syncthreads();

    float o_val = 0.f;
    if (tid < 256) {
        const int hh = tid >> 5;       // head
        const int ch = tid & 31;       // channel within head
        const float m0 = sm[hh], m1 = sm[hh + 8];
        const float M  = fmaxf(m0, m1);
        const float c0 = __expf(m0 - M), c1 = __expf(m1 - M);
        const float L  = sl[hh] * c0 + sl[hh + 8] * c1;
        o_val = (sacc[hh][ch] * c0 + sacc[hh + 8][ch] * c1) / L;
    }

    // ---- block LN over 256 channels (threads 0..255 hold o_val) ----
    __shared__ float sred[2][8];
    if (tid < 256) {
        float s = o_val, ss = o_val * o_val;
#pragma unroll
        for (int off = 16; off > 0; off >>= 1) {
            s  += __shfl_xor_sync(0xffffffffu, s,  off);
            ss += __shfl_xor_sync(0xffffffffu, ss, off);
        }
        if (lane == 0) { sred[0][w] = s; sred[1][w] = ss; }
    }
    __syncthreads();
    float ts = 0.f, tss = 0.f;
#pragma unroll
    for (int i = 0; i < 8; ++i) { ts += sred[0][i]; tss += sred[1][i]; }
    const float mu  = ts * (1.f / 256.f);
    const float var = tss * (1.f / 256.f) - mu * mu;
    const float rln = rsqrtf(var + EPS_LN);

    __shared__ float sn[D_SZ];
    if (tid < 256)
        sn[tid] = (o_val - mu) * rln * n_w[tid] + n_b[tid];
    __syncthreads();

    // ---- out @ Wp^T : 2 threads per output column (split K 128+128) ----
    const int c   = tid & 255;
    const int seg = tid >> 8;
    const float4* w4 = reinterpret_cast<const float4*>(Wp + (size_t)c * D_SZ + seg * 128);
    const float4* x4 = reinterpret_cast<const float4*>(sn + seg * 128);
    float a = 0.f;
#pragma unroll
    for (int d = 0; d < 32; ++d) {
        float4 wv = w4[d];
        float4 xv = x4[d];
        a = fmaf(wv.x, xv.x, a);
        a = fmaf(wv.y, xv.y, a);
        a = fmaf(wv.z, xv.z, a);
        a = fmaf(wv.w, xv.w, a);
    }
    __shared__ float part[256];
    if (seg == 1) part[c] = a;
    __syncthreads();
    if (seg == 0) out[b * D_SZ + c] = a + part[c];
}

// ============================================================================
extern "C" void kernel_launch(void* const* d_in, const int* in_sizes, int n_in,
                              void* d_out, int out_size)
{
    const float* x_q  = (const float*)d_in[0];
    const float* x_k  = (const float*)d_in[1];
    const float* x_v  = (const float*)d_in[2];
    const float* Wq   = (const float*)d_in[3];
    const float* Wk   = (const float*)d_in[4];
    const float* Wv   = (const float*)d_in[5];
    const float* Wp   = (const float*)d_in[6];
    const float* qn_w = (const float*)d_in[7];
    const float* qn_b = (const float*)d_in[8];
    const float* kn_w = (const float*)d_in[9];
    const float* kn_b = (const float*)d_in[10];
    const float* n_w  = (const float*)d_in[11];
    const float* n_b  = (const float*)d_in[12];
    float* out = (float*)d_out;

    cudaFuncSetAttribute(proj_mma,
                         cudaFuncAttributeMaxDynamicSharedMemorySize, DSM_B);

    const int M_TILES = (B_SZ * K_SZ) / 64;   // 8192

    wsplit_kernel<<<512, 256>>>(Wk, Wv);
    qproj_kernel<<<B_SZ, 256>>>(x_q, Wq, qn_w, qn_b);
    proj_mma<<<dim3(M_TILES, 2), PT, DSM_B>>>(x_k, x_v, kn_w, kn_b);
    attn_kernel<<<B_SZ, 512>>>(Wp, n_w, n_b, out);
}

// round 13
// speedup vs baseline: 1.6966x; 1.0602x over previous
#include <cuda_runtime.h>
#include <cuda_bf16.h>
#include <cuda_fp16.h>
#include <cstdint>

#define B_SZ   1024
#define K_SZ   512
#define D_SZ   256
#define H_SZ   8
#define HD_SZ  32
#define EPS_LN 1e-5f
#define Q_SCALE 0.17677669529663687f   // 32^-0.5

// ---------------- scratch (device globals; allocation-free) ----------------
__device__ float  g_q[B_SZ * D_SZ];                       // 1 MB
__device__ __half g_kh[(size_t)B_SZ * K_SZ * D_SZ];       // 256 MB (LN'd k, fp16)
__device__ __half g_vh[(size_t)B_SZ * K_SZ * D_SZ];       // 256 MB (v, fp16)
__device__ __half g_wh[2][D_SZ * D_SZ];                   // W fp16 (0=Wk,1=Wv)

// ======================= helpers ==============================
__device__ __forceinline__ uint32_t smem_u32(const void* p) {
    uint32_t a;
    asm("{ .reg .u64 t; cvta.to.shared.u64 t, %1; cvt.u32.u64 %0, t; }"
        : "=r"(a) : "l"(p));
    return a;
}
__device__ __forceinline__ uint32_t pack_h2(float a, float b) {
    __half2 t = __floats2half2_rn(a, b);
    return *reinterpret_cast<uint32_t*>(&t);
}

#define LDSM4(r0, r1, r2, r3, addr) \
    asm volatile("ldmatrix.sync.aligned.m8n8.x4.shared.b16 {%0,%1,%2,%3}, [%4];" \
                 : "=r"(r0), "=r"(r1), "=r"(r2), "=r"(r3) : "r"(addr))

#define MMA16816H(c, a, b) \
    asm volatile("mma.sync.aligned.m16n8k16.row.col.f32.f16.f16.f32 " \
                 "{%0,%1,%2,%3}, {%4,%5,%6,%7}, {%8,%9}, {%0,%1,%2,%3};" \
                 : "+f"((c)[0]), "+f"((c)[1]), "+f"((c)[2]), "+f"((c)[3]) \
                 : "r"((a)[0]), "r"((a)[1]), "r"((a)[2]), "r"((a)[3]), \
                   "r"((b)[0]), "r"((b)[1]))

#define CP16(dst, gsrc) \
    asm volatile("cp.async.ca.shared.global [%0], [%1], 16;" \
                 :: "r"(dst), "l"(gsrc) : "memory")
#define CP_COMMIT() asm volatile("cp.async.commit_group;" ::: "memory")
#define CP_WAIT0()  asm volatile("cp.async.wait_group 0;" ::: "memory")

// ============================================================================
// Kernel 0: convert Wk/Wv to fp16.  grid=512, block=256
// ============================================================================
__global__ void wsplit_kernel(const float* __restrict__ Wk,
                              const float* __restrict__ Wv)
{
    const int sel = blockIdx.x & 1;
    const int i   = (blockIdx.x >> 1) * 256 + threadIdx.x;
    g_wh[sel][i] = __float2half_rn((sel ? Wv : Wk)[i]);
}

// ============================================================================
// Kernel 1: q = LN_perhead(x_q @ Wq^T) * scale          grid=B, block=256
// ============================================================================
__global__ void qproj_kernel(const float* __restrict__ xq,
                             const float* __restrict__ Wq,
                             const float* __restrict__ qn_w,
                             const float* __restrict__ qn_b)
{
    const int b = blockIdx.x;
    const int j = threadIdx.x;
    const int lane = j & 31;

    __shared__ float xrow[D_SZ];
    xrow[j] = xq[b * D_SZ + j];
    __syncthreads();

    const float4* w4 = reinterpret_cast<const float4*>(Wq + (size_t)j * D_SZ);
    const float4* x4 = reinterpret_cast<const float4*>(xrow);
    float acc = 0.f;
#pragma unroll
    for (int d = 0; d < D_SZ / 4; ++d) {
        float4 w = w4[d];
        float4 x = x4[d];
        acc = fmaf(w.x, x.x, acc);
        acc = fmaf(w.y, x.y, acc);
        acc = fmaf(w.z, x.z, acc);
        acc = fmaf(w.w, x.w, acc);
    }
    float s = acc, ss = acc * acc;
#pragma unroll
    for (int o = 16; o > 0; o >>= 1) {
        s  += __shfl_xor_sync(0xffffffffu, s,  o);
        ss += __shfl_xor_sync(0xffffffffu, ss, o);
    }
    const float mu  = s * (1.f / 32.f);
    const float var = ss * (1.f / 32.f) - mu * mu;
    const float r   = rsqrtf(var + EPS_LN);
    float q = (acc - mu) * r * qn_w[lane] + qn_b[lane];
    g_q[b * D_SZ + j] = q * Q_SCALE;
}

// ============================================================================
// Kernel 2 (mma.sync fp16): both K and V projections in one launch.
//   grid=(4096, 2): blockIdx.y selects (X, W, LN?, Out).
//   CTA: 512 thr / 16 warps, M=128, N=256, K chunks 64, double-buffered smem.
//   Warp (mh = wid>>2, hs = wid&3) owns rows [32mh,+32) x cols [64hs,+64).
//   LN params loaded only in the epilogue (keeps mainloop under 128 regs).
// ============================================================================
#define CH       64
#define NCH      (D_SZ / CH)      // 4
#define OFF_A    0                 // 128 rows * 128B = 16 KB
#define OFF_W    16384             // 256 rows * 128B = 32 KB
#define STAGE_B  49152             // 48 KB per stage
#define DSM_B    (2 * STAGE_B + 1024)
#define PT       512

__global__ void __launch_bounds__(PT, 1)
proj_mma(const float* __restrict__ x_k, const float* __restrict__ x_v,
         const float* __restrict__ lnw, const float* __restrict__ lnb)
{
    extern __shared__ char dsm[];
    char* smp = (char*)((((uintptr_t)dsm) + 1023) & ~(uintptr_t)1023);
    const uint32_t base = smem_u32(smp);

    const int wsel = blockIdx.y;           // 0 = K (with LN), 1 = V
    const bool do_ln = (wsel == 0);
    const float* __restrict__ X = do_ln ? x_k : x_v;

    const int tid  = threadIdx.x;
    const int wid  = tid >> 5;
    const int lane = tid & 31;
    const int mh   = wid >> 2;       // 0..3 : 32-row stripe
    const int hs   = wid & 3;        // 0..3 : 64-col stripe (2 heads)
    const size_t m_base = (size_t)blockIdx.x * 128;

    const __half* __restrict__ Wh = g_wh[wsel];

    // ---- X load/convert mapping: thread -> row tid>>2, 16 floats ----
    const int xrow = tid >> 2;             // 0..127
    const int fgrp = tid & 3;              // 16-float group in 64-chunk
    const float* xptr = X + (m_base + xrow) * D_SZ + fgrp * 16;
    const uint32_t xb0   = (uint32_t)fgrp * 32u;
    const uint32_t xswz  = (uint32_t)(xrow & 7) * 16u;
    const uint32_t xoff0 = (uint32_t)xrow * 128u + (xb0 ^ xswz);
    const uint32_t xoff1 = (uint32_t)xrow * 128u + ((xb0 + 16u) ^ xswz);

    float acc[2][8][4];
#pragma unroll
    for (int i = 0; i < 2; ++i)
#pragma unroll
        for (int j = 0; j < 8; ++j)
#pragma unroll
            for (int cc = 0; cc < 4; ++cc) acc[i][j][cc] = 0.f;

    float4 xr[4];

    auto stage_x = [&](char* ab) {
        const float* xf = reinterpret_cast<const float*>(xr);
        uint4 h0, h1;
        h0.x = pack_h2(xf[0],  xf[1]);  h0.y = pack_h2(xf[2],  xf[3]);
        h0.z = pack_h2(xf[4],  xf[5]);  h0.w = pack_h2(xf[6],  xf[7]);
        h1.x = pack_h2(xf[8],  xf[9]);  h1.y = pack_h2(xf[10], xf[11]);
        h1.z = pack_h2(xf[12], xf[13]); h1.w = pack_h2(xf[14], xf[15]);
        *reinterpret_cast<uint4*>(ab + OFF_A + xoff0) = h0;
        *reinterpret_cast<uint4*>(ab + OFF_A + xoff1) = h1;
    };

    // ================= prologue: stage 0 = chunk 0 =================
    {
        const uint32_t wb = base;
#pragma unroll
        for (int i = 0; i < 4; ++i) {
            const int idx = tid + i * PT;
            const int row = idx >> 3;
            const int j16 = idx & 7;
            const uint32_t off = (uint32_t)row * 128u +
                                 (((uint32_t)j16 * 16u) ^ ((uint32_t)(row & 7) * 16u));
            CP16(wb + OFF_W + off, (const char*)Wh + (size_t)row * 512 + j16 * 16);
        }
        CP_COMMIT();
#pragma unroll
        for (int u = 0; u < 4; ++u)
            xr[u] = *reinterpret_cast<const float4*>(xptr + u * 4);
        stage_x(smp);
        CP_WAIT0();
        __syncthreads();
    }

    // ================= main loop over K chunks =================
    for (int c = 0; c < NCH; ++c) {
        const int s = c & 1;
        const uint32_t sb = base + s * STAGE_B;

        if (c + 1 < NCH) {
            const int kn = (c + 1) * CH;
            const uint32_t wb = base + (s ^ 1) * STAGE_B;
#pragma unroll
            for (int i = 0; i < 4; ++i) {
                const int idx = tid + i * PT;
                const int row = idx >> 3;
                const int j16 = idx & 7;
                const uint32_t off = (uint32_t)row * 128u +
                                     (((uint32_t)j16 * 16u) ^ ((uint32_t)(row & 7) * 16u));
                CP16(wb + OFF_W + off,
                     (const char*)Wh + (size_t)row * 512 + kn * 2 + j16 * 16);
            }
            CP_COMMIT();
#pragma unroll
            for (int u = 0; u < 4; ++u)
                xr[u] = *reinterpret_cast<const float4*>(xptr + kn + u * 4);
        }

        // ---------------- compute chunk c ----------------
#pragma unroll
        for (int ks = 0; ks < 4; ++ks) {
            uint32_t Ah4[2][4], Bh4[8][2];
            {
                const int ar = lane & 15;
                const uint32_t akhb = (uint32_t)(lane >> 4) * 16u;
#pragma unroll
                for (int i = 0; i < 2; ++i) {
                    const int row = 32 * mh + 16 * i + ar;
                    const uint32_t off = (uint32_t)row * 128u +
                        (((uint32_t)ks * 32u + akhb) ^ ((uint32_t)(row & 7) * 16u));
                    LDSM4(Ah4[i][0], Ah4[i][1], Ah4[i][2], Ah4[i][3], sb + OFF_A + off);
                }
            }
            {
                const int g2  = lane >> 3;
                const uint32_t khb = (uint32_t)(g2 & 1) * 16u;
                const int rsub = ((g2 >> 1) * 8) + (lane & 7);
#pragma unroll
                for (int p = 0; p < 4; ++p) {
                    const int row = hs * 64 + p * 16 + rsub;
                    const uint32_t off = (uint32_t)row * 128u +
                        (((uint32_t)ks * 32u + khb) ^ ((uint32_t)(row & 7) * 16u));
                    LDSM4(Bh4[2 * p][0], Bh4[2 * p][1], Bh4[2 * p + 1][0], Bh4[2 * p + 1][1],
                          sb + OFF_W + off);
                }
            }
#pragma unroll
            for (int i = 0; i < 2; ++i)
#pragma unroll
                for (int j = 0; j < 8; ++j)
                    MMA16816H(acc[i][j], Ah4[i], Bh4[j]);
        }

        // ---------------- stage X for chunk c+1 ----------------
        if (c + 1 < NCH) {
            stage_x(smp + (s ^ 1) * STAGE_B);
            CP_WAIT0();
        }
        __syncthreads();
    }

    // ================= epilogue: per-head LN + fp16 store =================
    __half* __restrict__ Out = do_ln ? g_kh : g_vh;
    const int g  = lane >> 2;
    const int tg = lane & 3;

    float lw[8][2], lb[8][2];
    if (do_ln) {
#pragma unroll
        for (int j = 0; j < 8; ++j) {
            const int c = (j & 3) * 8 + 2 * tg;   // channel-in-head
            lw[j][0] = lnw[c];     lw[j][1] = lnw[c + 1];
            lb[j][0] = lnb[c];     lb[j][1] = lnb[c + 1];
        }
    }

#pragma unroll
    for (int i = 0; i < 2; ++i) {
#pragma unroll
        for (int half = 0; half < 2; ++half) {
            const int r = 32 * mh + 16 * i + 8 * half + g;
            float v0[8], v1[8];
#pragma unroll
            for (int j = 0; j < 8; ++j) {
                v0[j] = acc[i][j][2 * half];
                v1[j] = acc[i][j][2 * half + 1];
            }
            if (do_ln) {
#pragma unroll
                for (int hd = 0; hd < 2; ++hd) {
                    float s = 0.f, ss = 0.f;
#pragma unroll
                    for (int jj = 0; jj < 4; ++jj) {
                        const int j = hd * 4 + jj;
                        s  += v0[j] + v1[j];
                        ss += v0[j] * v0[j] + v1[j] * v1[j];
                    }
                    s  += __shfl_xor_sync(0xffffffffu, s,  1);
                    ss += __shfl_xor_sync(0xffffffffu, ss, 1);
                    s  += __shfl_xor_sync(0xffffffffu, s,  2);
                    ss += __shfl_xor_sync(0xffffffffu, ss, 2);
                    const float mu  = s * (1.f / 32.f);
                    const float var = ss * (1.f / 32.f) - mu * mu;
                    const float rr  = rsqrtf(var + EPS_LN);
#pragma unroll
                    for (int jj = 0; jj < 4; ++jj) {
                        const int j = hd * 4 + jj;
                        v0[j] = (v0[j] - mu) * rr * lw[j][0] + lb[j][0];
                        v1[j] = (v1[j] - mu) * rr * lw[j][1] + lb[j][1];
                    }
                }
            }
            __half* orow = Out + (m_base + r) * D_SZ + hs * 64 + 2 * tg;
#pragma unroll
            for (int j = 0; j < 8; ++j)
                *reinterpret_cast<__half2*>(orow + 8 * j) = __floats2half2_rn(v0[j], v1[j]);
        }
    }
}

// ============================================================================
// Kernel 3: attention over fp16 k/v. grid=B, block=512, 2 CTAs/SM.
//   (unchanged from R11 — measured 154us, DRAM 44.5%)
// ============================================================================
__global__ void __launch_bounds__(512, 2)
attn_kernel(const float* __restrict__ Wp,
            const float* __restrict__ n_w,
            const float* __restrict__ n_b,
            float* __restrict__ out)
{
    const int b    = blockIdx.x;
    const int tid  = threadIdx.x;
    const int w    = tid >> 5;
    const int lane = tid & 31;
    const int h    = w & 7;
    const int khalf = w >> 3;      // 0/1 : K rows [0,256) or [256,512)
    const int rg   = lane >> 2;    // row within 8-row group
    const int cs   = lane & 3;     // 8-channel slice

    float qv[8];
    {
        const float4* qp = reinterpret_cast<const float4*>(
            g_q + b * D_SZ + h * HD_SZ + cs * 8);
        float4 a = qp[0], c = qp[1];
        qv[0] = a.x; qv[1] = a.y; qv[2] = a.z; qv[3] = a.w;
        qv[4] = c.x; qv[5] = c.y; qv[6] = c.z; qv[7] = c.w;
    }

    const __half* kbase = g_kh + (size_t)b * K_SZ * D_SZ + (size_t)khalf * 256 * D_SZ
                               + h * HD_SZ + cs * 8;
    const __half* vbase = g_vh + (size_t)b * K_SZ * D_SZ + (size_t)khalf * 256 * D_SZ
                               + h * HD_SZ + cs * 8;

    float m = -1e30f, l = 0.f;
    float acc[8];
#pragma unroll
    for (int e = 0; e < 8; ++e) acc[e] = 0.f;

    uint4 ka, va, kb, vb;

#define ALOAD(i, K, V) do {                                                    \
    const size_t roff = (size_t)((i) * 8 + rg) * D_SZ;                         \
    K = *reinterpret_cast<const uint4*>(kbase + roff);                         \
    V = *reinterpret_cast<const uint4*>(vbase + roff);                         \
} while (0)

#define ADOT(K, sres) do {                                                     \
    const __half2* kh = reinterpret_cast<const __half2*>(&K);                  \
    float s = 0.f;                                                             \
    _Pragma("unroll")                                                          \
    for (int e = 0; e < 4; ++e) {                                              \
        const float2 kf = __half22float2(kh[e]);                               \
        s = fmaf(qv[2 * e], kf.x, s);                                          \
        s = fmaf(qv[2 * e + 1], kf.y, s);                                      \
    }                                                                          \
    s += __shfl_xor_sync(0xffffffffu, s, 1);                                   \
    s += __shfl_xor_sync(0xffffffffu, s, 2);                                   \
    sres = s;                                                                  \
} while (0)

    ALOAD(0, ka, va);
#pragma unroll 1
    for (int it = 0; it < 32; it += 2) {
        ALOAD(it + 1, kb, vb);
        float s0, s1;
        ADOT(ka, s0);
        ADOT(kb, s1);

        const float mn   = fmaxf(m, fmaxf(s0, s1));
        const float corr = __expf(m - mn);
        const float p0   = __expf(s0 - mn);
        const float p1   = __expf(s1 - mn);
        l = l * corr + p0 + p1;
        const __half2* v0h = reinterpret_cast<const __half2*>(&va);
        const __half2* v1h = reinterpret_cast<const __half2*>(&vb);
#pragma unroll
        for (int e = 0; e < 4; ++e) {
            const float2 vf0 = __half22float2(v0h[e]);
            const float2 vf1 = __half22float2(v1h[e]);
            acc[2 * e]     = fmaf(acc[2 * e],     corr, p0 * vf0.x + p1 * vf1.x);
            acc[2 * e + 1] = fmaf(acc[2 * e + 1], corr, p0 * vf0.y + p1 * vf1.y);
        }
        m = mn;
        if (it + 2 < 32) ALOAD(it + 2, ka, va);
    }
#undef ALOAD
#undef ADOT

    // ---- intra-warp merge over 8 row-groups (lanes xor 4,8,16) ----
#pragma unroll
    for (int off = 4; off <= 16; off <<= 1) {
        const float pm = __shfl_xor_sync(0xffffffffu, m, off);
        const float pl = __shfl_xor_sync(0xffffffffu, l, off);
        const float MM = fmaxf(m, pm);
        const float ca = __expf(m - MM);
        const float cb = __expf(pm - MM);
        l = l * ca + pl * cb;
#pragma unroll
        for (int e = 0; e < 8; ++e) {
            const float pa = __shfl_xor_sync(0xffffffffu, acc[e], off);
            acc[e] = acc[e] * ca + pa * cb;
        }
        m = MM;
    }

    // ---- cross-warp merge (w and w+8 share a head) ----
    __shared__ float sm[16], sl[16];
    __shared__ float sacc[16][33];
    if (lane == 0) { sm[w] = m; sl[w] = l; }
    if (rg == 0) {
#pragma unroll
        for (int e = 0; e < 8; ++e) sacc[w][cs * 8 + e] = acc[e];
    }
    __syncthreads();

    float o_val = 0.f;
    if (tid < 256) {
        const int hh = tid >> 5;       // head
        const int ch = tid & 31;       // channel within head
        const float m0 = sm[hh], m1 = sm[hh + 8];
        const float M  = fmaxf(m0, m1);
        const float c0 = __expf(m0 - M), c1 = __expf(m1 - M);
        const float L  = sl[hh] * c0 + sl[hh + 8] * c1;
        o_val = (sacc[hh][ch] * c0 + sacc[hh + 8][ch] * c1) / L;
    }

    // ---- block LN over 256 channels (threads 0..255 hold o_val) ----
    __shared__ float sred[2][8];
    if (tid < 256) {
        float s = o_val, ss = o_val * o_val;
#pragma unroll
        for (int off = 16; off > 0; off >>= 1) {
            s  += __shfl_xor_sync(0xffffffffu, s,  off);
            ss += __shfl_xor_sync(0xffffffffu, ss, off);
        }
        if (lane == 0) { sred[0][w] = s; sred[1][w] = ss; }
    }
    __syncthreads();
    float ts = 0.f, tss = 0.f;
#pragma unroll
    for (int i = 0; i < 8; ++i) { ts += sred[0][i]; tss += sred[1][i]; }
    const float mu  = ts * (1.f / 256.f);
    const float var = tss * (1.f / 256.f) - mu * mu;
    const float rln = rsqrtf(var + EPS_LN);

    __shared__ float sn[D_SZ];
    if (tid < 256)
        sn[tid] = (o_val - mu) * rln * n_w[tid] + n_b[tid];
    __syncthreads();

    // ---- out @ Wp^T : 2 threads per output column (split K 128+128) ----
    const int c   = tid & 255;
    const int seg = tid >> 8;
    const float4* w4 = reinterpret_cast<const float4*>(Wp + (size_t)c * D_SZ + seg * 128);
    const float4* x4 = reinterpret_cast<const float4*>(sn + seg * 128);
    float a = 0.f;
#pragma unroll
    for (int d = 0; d < 32; ++d) {
        float4 wv = w4[d];
        float4 xv = x4[d];
        a = fmaf(wv.x, xv.x, a);
        a = fmaf(wv.y, xv.y, a);
        a = fmaf(wv.z, xv.z, a);
        a = fmaf(wv.w, xv.w, a);
    }
    __shared__ float part[256];
    if (seg == 1) part[c] = a;
    __syncthreads();
    if (seg == 0) out[b * D_SZ + c] = a + part[c];
}

// ============================================================================
extern "C" void kernel_launch(void* const* d_in, const int* in_sizes, int n_in,
                              void* d_out, int out_size)
{
    const float* x_q  = (const float*)d_in[0];
    const float* x_k  = (const float*)d_in[1];
    const float* x_v  = (const float*)d_in[2];
    const float* Wq   = (const float*)d_in[3];
    const float* Wk   = (const float*)d_in[4];
    const float* Wv   = (const float*)d_in[5];
    const float* Wp   = (const float*)d_in[6];
    const float* qn_w = (const float*)d_in[7];
    const float* qn_b = (const float*)d_in[8];
    const float* kn_w = (const float*)d_in[9];
    const float* kn_b = (const float*)d_in[10];
    const float* n_w  = (const float*)d_in[11];
    const float* n_b  = (const float*)d_in[12];
    float* out = (float*)d_out;

    cudaFuncSetAttribute(proj_mma,
                         cudaFuncAttributeMaxDynamicSharedMemorySize, DSM_B);

    const int M_TILES = (B_SZ * K_SZ) / 128;   // 4096

    wsplit_kernel<<<512, 256>>>(Wk, Wv);
    qproj_kernel<<<B_SZ, 256>>>(x_q, Wq, qn_w, qn_b);
    proj_mma<<<dim3(M_TILES, 2), PT, DSM_B>>>(x_k, x_v, kn_w, kn_b);
    attn_kernel<<<B_SZ, 512>>>(Wp, n_w, n_b, out);
}